// round 16
// baseline (speedup 1.0000x reference)
#include <cuda_runtime.h>
#include <cstdint>
#include <cstddef>

#define CN 128
#define HN 256
#define TN 4
#define SN 57
#define PN 10
#define BK 32
#define ST 132   // padded smem stride: 528B/row, 16B-aligned for LDS.128 at every k

// ---------------- scratch (device globals; no allocation) ----------------
__device__ float g_cf[CN*HN];          // cf (C,H)
__device__ float g_pg[CN*HN];          // pg (C,H)
__device__ float g_AB[CN*2*HN];        // [A | B+bel]  (C,512)
__device__ float g_gy[CN*HN];          // geo pre-GN
__device__ float g_E [CN*CN*2*HN];     // E (C*C, 512) 33.5MB
__device__ float g_UV[CN*2*HN];        // [U+bne | V] (C,512)
__device__ float g_ch[CN*HN];
__device__ float g_x1[CN*HN];
__device__ float g_x2[CN*HN];
__device__ int   g_ok[CN];
__device__ float g_warm[64*256];       // sink for L2-warm role

__device__ __forceinline__ float lrelu(float x){ return x > 0.f ? x : 0.01f*x; }

__device__ __forceinline__ float2 fma2(float2 a, float2 b, float2 c) {
    unsigned long long au = *reinterpret_cast<unsigned long long*>(&a);
    unsigned long long bu = *reinterpret_cast<unsigned long long*>(&b);
    unsigned long long cu = *reinterpret_cast<unsigned long long*>(&c);
    unsigned long long du;
    asm("fma.rn.f32x2 %0, %1, %2, %3;" : "=l"(du) : "l"(au), "l"(bu), "l"(cu));
    return *reinterpret_cast<float2*>(&du);
}

// ---------------- 1. big GEMVs: cf and pg (32768 outs each, K=256) --------
__global__ void k_gemv_big(const float* __restrict__ psf, const float* __restrict__ Wp,
                           const float* __restrict__ bp,  const float* __restrict__ pgf,
                           const float* __restrict__ Wgp, const float* __restrict__ bgp) {
    __shared__ float sin_[HN];
    bool second = blockIdx.x >= 512;
    const float* in = second ? pgf : psf;
    const float* W  = second ? Wgp : Wp;
    const float* b  = second ? bgp : bp;
    float* out      = second ? g_pg : g_cf;
    int base = (blockIdx.x & 511) * 64;
    sin_[threadIdx.x] = in[threadIdx.x];
    __syncthreads();
    int warp = threadIdx.x >> 5, lane = threadIdx.x & 31;
    #pragma unroll
    for (int rr = 0; rr < 8; rr++) {
        int r = base + warp*8 + rr;
        const float* wr = W + (size_t)r * HN;
        float s = 0.f;
        #pragma unroll
        for (int q = 0; q < 2; q++) {
            float4 wv = *(const float4*)&wr[lane*4 + 128*q];
            float4 xv = *(const float4*)&sin_[lane*4 + 128*q];
            s += wv.x*xv.x + wv.y*xv.y + wv.z*xv.z + wv.w*xv.w;
        }
        #pragma unroll
        for (int o = 16; o; o >>= 1) s += __shfl_down_sync(0xffffffffu, s, o);
        if (lane == 0) out[r] = lrelu(s + b[r]);
    }
}

// ---------------- sgemm body: tiled 32x32x32, double-buffered --------------
template<int MODE>
__device__ __forceinline__ void sgemm_body(char* sh,
                                           const float* __restrict__ W,
                                           const float* __restrict__ b1,
                                           float* __restrict__ out, int it,
                                           int bn, int bm) {
    constexpr int K  = (MODE == 3) ? 768 : 256;
    constexpr int NT = K / 32;
    typedef float (*tile_t)[32][33];
    tile_t Xs = (tile_t)sh;                     // [2][32][33]
    tile_t Ws = (tile_t)(sh + 2*32*33*4);       // [2][32][33]
    int tid = threadIdx.x;
    int r  = tid >> 3, c4 = (tid & 7) * 4;
    int tx = tid & 15, ty = tid >> 4;
    int m0 = bm*32 + r;
    int n0 = bn*32 + r;

    const float* wrow;
    if      (MODE == 0) wrow = W + (n0 < 256 ? (size_t)n0*512 : (size_t)(n0-256)*512 + 256);
    else if (MODE == 1) wrow = W + (size_t)n0*256;
    else if (MODE == 2) wrow = W + ((size_t)it*256 + (n0 & 255))*772 + (n0 >= 256 ? 256 : 0);
    else if (MODE == 3) wrow = W + (size_t)n0*768;
    else                wrow = W + (size_t)n0*256;

    const float* Xbase;
    if      (MODE == 0) Xbase = g_cf;
    else if (MODE == 1) Xbase = g_pg;
    else if (MODE == 2) Xbase = it ? g_x1 : g_cf;
    else if (MODE == 4) Xbase = g_ch;
    else                Xbase = g_cf;

    auto loadX = [&](int kb) -> float4 {
        if (MODE == 3) {
            int g = kb + c4;
            const float* src = (g < 256) ? g_cf : (g < 512 ? g_x1 : g_x2);
            return *(const float4*)(src + (size_t)m0*256 + (g & 255));
        }
        return *(const float4*)(Xbase + (size_t)m0*256 + kb + c4);
    };

    float4 xv = loadX(0);
    float4 wv = *(const float4*)(wrow + c4);
    float a00 = 0.f, a01 = 0.f, a10 = 0.f, a11 = 0.f;

    for (int t = 0; t < NT; t++) {
        int cur = t & 1;
        Xs[cur][c4+0][r] = xv.x; Xs[cur][c4+1][r] = xv.y;
        Xs[cur][c4+2][r] = xv.z; Xs[cur][c4+3][r] = xv.w;
        Ws[cur][c4+0][r] = wv.x; Ws[cur][c4+1][r] = wv.y;
        Ws[cur][c4+2][r] = wv.z; Ws[cur][c4+3][r] = wv.w;
        __syncthreads();
        if (t + 1 < NT) {
            xv = loadX((t+1)*32);
            wv = *(const float4*)(wrow + (t+1)*32 + c4);
        }
        #pragma unroll
        for (int k = 0; k < 32; k++) {
            float ax = Xs[cur][k][ty*2], ay = Xs[cur][k][ty*2+1];
            float bx = Ws[cur][k][tx*2], by = Ws[cur][k][tx*2+1];
            a00 += ax*bx; a01 += ax*by;
            a10 += ay*bx; a11 += ay*by;
        }
        if (t + 1 < NT) __syncthreads();
    }

    int m = bm*32 + ty*2, n = bn*32 + tx*2;
    float accs[2][2] = {{a00, a01}, {a10, a11}};
    #pragma unroll
    for (int mi = 0; mi < 2; mi++) {
        #pragma unroll
        for (int ni = 0; ni < 2; ni++) {
            int mm = m + mi, nn = n + ni;
            float v = accs[mi][ni];
            if      (MODE == 0) g_AB[mm*512 + nn] = (nn >= 256) ? v + b1[nn-256] : v;
            else if (MODE == 1) g_gy[mm*256 + nn] = v + b1[nn];
            else if (MODE == 2) g_UV[mm*512 + nn] = (nn < 256) ? v + b1[it*256 + nn] : v;
            else if (MODE == 3) g_ch[mm*256 + nn] = lrelu(v + b1[nn]);
            else                out [mm*256 + nn] = lrelu(v + b1[nn]);
        }
    }
}

// ---------------- heads body: one warp per (i, o) ---------------------------
__device__ __forceinline__ void heads_body(const float* __restrict__ We,  const float* __restrict__ be,
                                           const float* __restrict__ Ws,  const float* __restrict__ bs,
                                           const float* __restrict__ Wsi, const float* __restrict__ bsi,
                                           float* __restrict__ o_sem, float* __restrict__ o_semins,
                                           float* __restrict__ o_exists, int i, int oy) {
    int lane = threadIdx.x & 31, warp = threadIdx.x >> 5;
    int o = oy * 8 + warp;
    if (o > SN + PN) return;
    const float* w; float bias;
    if (o < SN)           { w = Ws  + o*HN;       bias = bs[o]; }
    else if (o < SN + PN) { w = Wsi + (o-SN)*HN;  bias = bsi[o-SN]; }
    else                  { w = We;               bias = be[0]; }
    float4 x0 = *(const float4*)&g_cf[i*HN + lane*4];
    float4 x1 = *(const float4*)&g_cf[i*HN + 128 + lane*4];
    float4 w0 = *(const float4*)&w[lane*4];
    float4 w1 = *(const float4*)&w[128 + lane*4];
    float s = w0.x*x0.x + w0.y*x0.y + w0.z*x0.z + w0.w*x0.w
            + w1.x*x1.x + w1.y*x1.y + w1.z*x1.z + w1.w*x1.w;
    #pragma unroll
    for (int q = 16; q; q >>= 1) s += __shfl_xor_sync(0xffffffffu, s, q);
    if (lane == 0) {
        s += bias;
        if (o < SN)           o_sem[i*SN + o] = s;
        else if (o < SN + PN) o_semins[i*PN + (o-SN)] = s;
        else { o_exists[i] = s; g_ok[i] = (s > 0.f) ? 1 : 0; }
    }
}

// ---------------- gemm body: E = el @ W3^T, BK=32, reg pipeline ------------
__device__ __forceinline__ void gemm_body(char* sh, const float* __restrict__ Wne,
                                          int bm, int bn) {
    if (g_ok[bm] == 0) return;
    typedef float (*buf_t)[BK*ST];
    buf_t As = (buf_t)sh;                       // [2][BK*ST]
    buf_t Bs = (buf_t)(sh + 2*BK*ST*4);
    int tid = threadIdx.x;
    int tx = tid & 15, ty = tid >> 4;

    float4 va[4], vb[4];
    int lm[4], lc[4];
    #pragma unroll
    for (int q = 0; q < 4; q++) { int l = tid + 256*q; lm[q] = l >> 3; lc[q] = (l & 7)*4; }

    auto ld = [&](int kb) {
        #pragma unroll
        for (int q = 0; q < 4; q++) {
            float4 a = *(const float4*)&g_AB[bm*512 + kb + lc[q]];
            float4 b = *(const float4*)&g_AB[lm[q]*512 + 256 + kb + lc[q]];
            va[q].x = lrelu(a.x + b.x);
            va[q].y = lrelu(a.y + b.y);
            va[q].z = lrelu(a.z + b.z);
            va[q].w = lrelu(a.w + b.w);
            int ng = bn*128 + lm[q];
            vb[q] = *(const float4*)&Wne[(size_t)ng*772 + 512 + kb + lc[q]];
        }
    };
    auto sts = [&](int s) {
        #pragma unroll
        for (int q = 0; q < 4; q++) {
            As[s][(lc[q]+0)*ST + lm[q]] = va[q].x;
            As[s][(lc[q]+1)*ST + lm[q]] = va[q].y;
            As[s][(lc[q]+2)*ST + lm[q]] = va[q].z;
            As[s][(lc[q]+3)*ST + lm[q]] = va[q].w;
            Bs[s][(lc[q]+0)*ST + lm[q]] = vb[q].x;
            Bs[s][(lc[q]+1)*ST + lm[q]] = vb[q].y;
            Bs[s][(lc[q]+2)*ST + lm[q]] = vb[q].z;
            Bs[s][(lc[q]+3)*ST + lm[q]] = vb[q].w;
        }
    };

    float2 c[8][4];
    #pragma unroll
    for (int a = 0; a < 8; a++)
        #pragma unroll
        for (int q = 0; q < 4; q++) c[a][q] = make_float2(0.f, 0.f);

    ld(0);
    sts(0);
    constexpr int NT = HN / BK;
    for (int t = 0; t < NT; t++) {
        int cur = t & 1;
        __syncthreads();
        if (t + 1 < NT) ld((t+1)*BK);

        float4 fa[2][2], fb[2][2];
        fa[0][0] = *(const float4*)&As[cur][ty*4];
        fa[0][1] = *(const float4*)&As[cur][ty*4 + 64];
        fb[0][0] = *(const float4*)&Bs[cur][tx*4];
        fb[0][1] = *(const float4*)&Bs[cur][tx*4 + 64];
        #pragma unroll
        for (int k = 0; k < BK; k++) {
            int pb = k & 1, nb2 = pb ^ 1;
            if (k + 1 < BK) {
                fa[nb2][0] = *(const float4*)&As[cur][(k+1)*ST + ty*4];
                fa[nb2][1] = *(const float4*)&As[cur][(k+1)*ST + ty*4 + 64];
                fb[nb2][0] = *(const float4*)&Bs[cur][(k+1)*ST + tx*4];
                fb[nb2][1] = *(const float4*)&Bs[cur][(k+1)*ST + tx*4 + 64];
            }
            float am[8] = {fa[pb][0].x, fa[pb][0].y, fa[pb][0].z, fa[pb][0].w,
                           fa[pb][1].x, fa[pb][1].y, fa[pb][1].z, fa[pb][1].w};
            float2 bl[4] = {make_float2(fb[pb][0].x, fb[pb][0].y),
                            make_float2(fb[pb][0].z, fb[pb][0].w),
                            make_float2(fb[pb][1].x, fb[pb][1].y),
                            make_float2(fb[pb][1].z, fb[pb][1].w)};
            #pragma unroll
            for (int mi = 0; mi < 8; mi++) {
                float2 a2 = make_float2(am[mi], am[mi]);
                #pragma unroll
                for (int qn = 0; qn < 4; qn++)
                    c[mi][qn] = fma2(a2, bl[qn], c[mi][qn]);
            }
        }
        if (t + 1 < NT) sts(cur ^ 1);
    }
    #pragma unroll
    for (int mi = 0; mi < 8; mi++) {
        int m = bm*128 + ty*4 + (mi>>2)*64 + (mi&3);
        float* Erow = g_E + (size_t)m*512 + bn*128;
        float4 v0, v1;
        v0.x = c[mi][0].x; v0.y = c[mi][0].y; v0.z = c[mi][1].x; v0.w = c[mi][1].y;
        v1.x = c[mi][2].x; v1.y = c[mi][2].y; v1.z = c[mi][3].x; v1.w = c[mi][3].y;
        *(float4*)&Erow[tx*4]      = v0;
        *(float4*)&Erow[tx*4 + 64] = v1;
    }
}

// ---------------- el body: edge logits ------------------------------------
__device__ __forceinline__ void el_body(char* sh, const float* __restrict__ Wee,
                                        const float* __restrict__ bee,
                                        float* __restrict__ o_logits, int i) {
    float* sA = (float*)sh;                     // 256
    float* sW = sA + 256;                       // 1024
    float* sB = sW + 1024;                      // 128*33
    float* sP = sB + 128*33;                    // 1024
    int t = threadIdx.x;
    int j = t & 127, half = t >> 7;
    sA[t] = g_AB[i*512 + t];
    #pragma unroll
    for (int l = t; l < 1024; l += 256) sW[l] = Wee[l];
    float acc0 = 0.f, acc1 = 0.f, acc2 = 0.f, acc3 = 0.f;
    for (int c0 = 0; c0 < 256; c0 += 32) {
        __syncthreads();
        #pragma unroll
        for (int idx = t; idx < 1024; idx += 256) {
            int jj = idx >> 3, f4 = (idx & 7) * 4;
            float4 v = *(const float4*)&g_AB[jj*512 + 256 + c0 + f4];
            sB[jj*33 + f4+0] = v.x; sB[jj*33 + f4+1] = v.y;
            sB[jj*33 + f4+2] = v.z; sB[jj*33 + f4+3] = v.w;
        }
        __syncthreads();
        int h0 = half*16;
        #pragma unroll
        for (int hh = 0; hh < 16; hh++) {
            int h = h0 + hh;
            float e = lrelu(sA[c0+h] + sB[j*33 + h]);
            acc0 += e * sW[        c0+h];
            acc1 += e * sW[256  + c0+h];
            acc2 += e * sW[512  + c0+h];
            acc3 += e * sW[768  + c0+h];
        }
    }
    sP[(j*2+half)*4 + 0] = acc0;
    sP[(j*2+half)*4 + 1] = acc1;
    sP[(j*2+half)*4 + 2] = acc2;
    sP[(j*2+half)*4 + 3] = acc3;
    __syncthreads();
    if (t < 128) {
        float4 o;
        o.x = sP[t*8+0] + sP[t*8+4] + bee[0];
        o.y = sP[t*8+1] + sP[t*8+5] + bee[1];
        o.z = sP[t*8+2] + sP[t*8+6] + bee[2];
        o.w = sP[t*8+3] + sP[t*8+7] + bee[3];
        *(float4*)&o_logits[(i*128 + t)*4] = o;
    }
}

// ---------------- gn body: groupnorm + lrelu -------------------------------
__device__ __forceinline__ void gn_body(char* sh, const float* __restrict__ gw,
                                        const float* __restrict__ gb,
                                        float* __restrict__ outg, int i) {
    float* sy = (float*)sh;       // 256
    float* sm = sy + 256;         // 32
    float* sv = sm + 32;          // 32
    int h = threadIdx.x;
    float s = g_gy[i*HN + h];
    sy[h] = s;
    __syncthreads();
    if (h < 32) {
        float m = 0.f, v = 0.f;
        #pragma unroll
        for (int q = 0; q < 8; q++) { float y = sy[h*8+q]; m += y; v += y*y; }
        m *= 0.125f; v = v*0.125f - m*m;
        sm[h] = m; sv[h] = rsqrtf(v + 1e-5f);
    }
    __syncthreads();
    float xn = (s - sm[h>>3]) * sv[h>>3] * gw[h] + gb[h];
    outg[i*HN + h] = lrelu(xn);
}

// ---------------- warm body: pull UV-it1 Wne region into L2 ----------------
__device__ __forceinline__ void warm_body(const float* __restrict__ Wne, int wb) {
    int t = threadIdx.x;
    int row = 256 + wb*4 + (t >> 6);
    int c0 = (t & 63) * 8;
    const float* src = Wne + (size_t)row*772 + c0;
    float4 a = *(const float4*)src;
    float4 b = *(const float4*)(src + 4);
    g_warm[wb*256 + t] = a.x + a.y + a.z + a.w + b.x + b.y + b.z + b.w;
}

// ---------------- zero body: clear x1/x2 for atomicMax merge ---------------
__device__ __forceinline__ void zero_body(int zb) {
    int t = threadIdx.x;
    float* dst = (zb < 32) ? g_x1 : g_x2;
    int off = (zb & 31) * 1024 + t * 4;
    *(float4*)&dst[off] = make_float4(0.f, 0.f, 0.f, 0.f);
}

// ---------------- L2: fused AB-sgemm + geo-sgemm + UV0 + heads -------------
__global__ void __launch_bounds__(256) k_stage2(
        const float* __restrict__ Wel, const float* __restrict__ bel,
        const float* __restrict__ Wgc, const float* __restrict__ bgc,
        const float* __restrict__ Wne, const float* __restrict__ bne,
        const float* __restrict__ We,  const float* __restrict__ be,
        const float* __restrict__ Ws,  const float* __restrict__ bs,
        const float* __restrict__ Wsi, const float* __restrict__ bsi,
        float* __restrict__ o_sem, float* __restrict__ o_semins,
        float* __restrict__ o_exists) {
    __shared__ __align__(16) char sh[2*2*32*33*4];
    int bid = blockIdx.x;
    if (bid < 64) {
        sgemm_body<0>(sh, Wel, bel, nullptr, 0, bid & 15, bid >> 4);
    } else if (bid < 128) {
        int b = bid - 64;
        sgemm_body<2>(sh, Wne, bne, nullptr, 0, b & 15, b >> 4);   // U|V it=0
    } else if (bid < 160) {
        int b = bid - 128;
        sgemm_body<1>(sh, Wgc, bgc, nullptr, 0, b & 7, b >> 3);
    } else {
        int hb = bid - 160;          // 0..1151
        heads_body(We, be, Ws, bs, Wsi, bsi, o_sem, o_semins, o_exists,
                   hb & 127, hb >> 7);
    }
}

// ---------------- L3: fused E-gemm + el + gn + warm + zero -----------------
__global__ void __launch_bounds__(256, 2) k_stage3(
        const float* __restrict__ Wne,
        const float* __restrict__ Wee, const float* __restrict__ bee,
        float* __restrict__ o_logits,
        const float* __restrict__ gw, const float* __restrict__ gb,
        float* __restrict__ o_geo) {
    __shared__ __align__(16) char sh[2*2*BK*ST*4];
    int bid = blockIdx.x;
    if (bid < 512) {
        gemm_body(sh, Wne, bid >> 2, bid & 3);
    } else if (bid < 640) {
        el_body(sh, Wee, bee, o_logits, bid - 512);
    } else if (bid < 768) {
        gn_body(sh, gw, gb, o_geo, bid - 640);
    } else if (bid < 832) {
        warm_body(Wne, bid - 768);
    } else {
        zero_body(bid - 832);
    }
}

// ---------------- standalone sgemm kernel (UV1 / heads1 / heads2) ----------
template<int MODE>
__global__ void __launch_bounds__(256) k_sgemm(const float* __restrict__ W,
                                               const float* __restrict__ b1,
                                               float* __restrict__ out, int it) {
    __shared__ __align__(16) char sh[2*2*32*33*4];
    sgemm_body<MODE>(sh, W, b1, out, it, blockIdx.x, blockIdx.y);
}

// ---------------- masked max-reduction v4: 2 blocks/i + atomicMax ----------
__global__ void __launch_bounds__(1024) k_reduce(const float* __restrict__ o_logits,
                                                 const float* __restrict__ Wne, int it) {
    int i = blockIdx.x >> 1, half = blockIdx.x & 1;
    int tid = threadIdx.x;
    int h = tid & 255, jh = tid >> 8;          // jh = 0..3
    float* xout = (it == 0) ? g_x1 : g_x2;     // pre-zeroed in stage3
    __shared__ float slog[CN*TN];
    __shared__ float sP[4*HN];
    if (tid < CN*TN) {
        float v = o_logits[i*CN*TN + tid];
        slog[tid] = g_ok[tid >> 2] ? v : -1.f;
    }
    __syncthreads();
    if (!g_ok[i]) return;                      // zeros already correct
    const float* wr = Wne + ((size_t)it*HN + h)*772 + 768;
    float w40 = wr[0], w41 = wr[1], w42 = wr[2], w43 = wr[3];
    float uh = g_UV[i*512 + h];
    const float* Ep = g_E + (size_t)i*CN*512 + it*HN + h;
    const float NEGINF = __int_as_float(0xff800000);
    float acc = NEGINF;
    int j0 = half*64 + jh*16;
    #pragma unroll 8
    for (int jj = 0; jj < 16; jj++) {
        int j = j0 + jj;
        float l0 = slog[j*4+0], l1 = slog[j*4+1], l2 = slog[j*4+2], l3 = slog[j*4+3];
        float b0 = l0 > 0.f ? l0*w40 : NEGINF;
        float b1 = l1 > 0.f ? l1*w41 : NEGINF;
        float b2 = l2 > 0.f ? l2*w42 : NEGINF;
        float b3 = l3 > 0.f ? l3*w43 : NEGINF;
        float best = fmaxf(fmaxf(b0, b1), fmaxf(b2, b3));
        float z = uh + g_UV[j*512 + 256 + h] + Ep[(size_t)j*512];
        acc = fmaxf(acc, best + z);
    }
    sP[jh*HN + h] = acc;
    __syncthreads();
    if (jh == 0) {
        float m = fmaxf(fmaxf(sP[h], sP[HN + h]), fmaxf(sP[2*HN + h], sP[3*HN + h]));
        float val = fmaxf(m, 0.f);             // >= 0: int-ordered
        atomicMax((int*)&xout[i*HN + h], __float_as_int(val));
    }
}

// ---------------- launch ---------------------------------------------------
extern "C" void kernel_launch(void* const* d_in, const int* in_sizes, int n_in,
                              void* d_out, int out_size) {
    const float* psf = (const float*)d_in[0];
    const float* pgf = (const float*)d_in[1];
    const float* Wp  = (const float*)d_in[2];
    const float* bp  = (const float*)d_in[3];
    const float* We  = (const float*)d_in[4];
    const float* be  = (const float*)d_in[5];
    const float* Ws  = (const float*)d_in[6];
    const float* bs  = (const float*)d_in[7];
    const float* Wsi = (const float*)d_in[8];
    const float* bsi = (const float*)d_in[9];
    const float* Wel = (const float*)d_in[10];
    const float* bel = (const float*)d_in[11];
    const float* Wee = (const float*)d_in[12];
    const float* bee = (const float*)d_in[13];
    const float* Wne = (const float*)d_in[14];
    const float* bne = (const float*)d_in[15];
    const float* Wc  = (const float*)d_in[16];
    const float* bc  = (const float*)d_in[17];
    const float* Wc2 = (const float*)d_in[18];
    const float* bc2 = (const float*)d_in[19];
    const float* Wgc = (const float*)d_in[20];
    const float* bgc = (const float*)d_in[21];
    const float* Wgp = (const float*)d_in[22];
    const float* bgp = (const float*)d_in[23];
    const float* gw  = (const float*)d_in[24];
    const float* gb  = (const float*)d_in[25];

    float* out       = (float*)d_out;
    float* o_child   = out;                    // 32768
    float* o_geo     = out + 32768;            // 32768
    float* o_sem     = out + 65536;            // 7296
    float* o_semins  = out + 72832;            // 1280
    float* o_exists  = out + 74112;            // 128
    float* o_logits  = out + 74240;            // 65536

    k_gemv_big<<<1024, 256>>>(psf, Wp, bp, pgf, Wgp, bgp);              // 1
    k_stage2<<<1312, 256>>>(Wel, bel, Wgc, bgc, Wne, bne, We, be,
                            Ws, bs, Wsi, bsi, o_sem, o_semins, o_exists); // 2 (+UV0)
    k_stage3<<<896, 256>>>(Wne, Wee, bee, o_logits, gw, gb, o_geo);     // 3 (+warm+zero)
    k_reduce<<<2*CN, 1024>>>(o_logits, Wne, 0);                         // 4
    k_sgemm<2><<<dim3(16, 4), 256>>>(Wne, bne, nullptr, 1);             // 5  U|V it=1
    k_reduce<<<2*CN, 1024>>>(o_logits, Wne, 1);                         // 6
    k_sgemm<3><<<dim3(8, 4), 256>>>(Wc, bc, nullptr, 0);                // 7  head1
    k_sgemm<4><<<dim3(8, 4), 256>>>(Wc2, bc2, o_child, 0);              // 8  head2
}

// round 17
// speedup vs baseline: 1.0683x; 1.0683x over previous
#include <cuda_runtime.h>
#include <cstdint>
#include <cstddef>

#define CN 128
#define HN 256
#define TN 4
#define SN 57
#define PN 10
#define BK 32
#define ST 132   // padded smem stride: 528B/row, 16B-aligned for LDS.128 at every k

// ---------------- scratch (device globals; no allocation) ----------------
__device__ float g_cf[CN*HN];          // cf (C,H)
__device__ float g_pg[CN*HN];          // pg (C,H)
__device__ float g_AB[CN*2*HN];        // [A | B+bel]  (C,512)
__device__ float g_gy[CN*HN];          // geo pre-GN
__device__ float g_E [CN*CN*2*HN];     // E (C*C, 512) 33.5MB
__device__ float g_UV[CN*2*HN];        // [U+bne | V] (C,512)
__device__ float g_ch[CN*HN];
__device__ float g_x1[CN*HN];
__device__ float g_x2[CN*HN];
__device__ int   g_ok[CN];
__device__ float g_warm[64*256];       // sink for L2-warm role

__device__ __forceinline__ float lrelu(float x){ return x > 0.f ? x : 0.01f*x; }

__device__ __forceinline__ float2 fma2(float2 a, float2 b, float2 c) {
    unsigned long long au = *reinterpret_cast<unsigned long long*>(&a);
    unsigned long long bu = *reinterpret_cast<unsigned long long*>(&b);
    unsigned long long cu = *reinterpret_cast<unsigned long long*>(&c);
    unsigned long long du;
    asm("fma.rn.f32x2 %0, %1, %2, %3;" : "=l"(du) : "l"(au), "l"(bu), "l"(cu));
    return *reinterpret_cast<float2*>(&du);
}

// ---------------- 1. big GEMVs: cf and pg (32768 outs each, K=256) --------
__global__ void k_gemv_big(const float* __restrict__ psf, const float* __restrict__ Wp,
                           const float* __restrict__ bp,  const float* __restrict__ pgf,
                           const float* __restrict__ Wgp, const float* __restrict__ bgp) {
    __shared__ float sin_[HN];
    bool second = blockIdx.x >= 512;
    const float* in = second ? pgf : psf;
    const float* W  = second ? Wgp : Wp;
    const float* b  = second ? bgp : bp;
    float* out      = second ? g_pg : g_cf;
    int base = (blockIdx.x & 511) * 64;
    sin_[threadIdx.x] = in[threadIdx.x];
    __syncthreads();
    int warp = threadIdx.x >> 5, lane = threadIdx.x & 31;
    #pragma unroll
    for (int rr = 0; rr < 8; rr++) {
        int r = base + warp*8 + rr;
        const float* wr = W + (size_t)r * HN;
        float s = 0.f;
        #pragma unroll
        for (int q = 0; q < 2; q++) {
            float4 wv = *(const float4*)&wr[lane*4 + 128*q];
            float4 xv = *(const float4*)&sin_[lane*4 + 128*q];
            s += wv.x*xv.x + wv.y*xv.y + wv.z*xv.z + wv.w*xv.w;
        }
        #pragma unroll
        for (int o = 16; o; o >>= 1) s += __shfl_down_sync(0xffffffffu, s, o);
        if (lane == 0) out[r] = lrelu(s + b[r]);
    }
}

// ---------------- sgemm body: tiled 32x32x32, double-buffered --------------
template<int MODE>
__device__ __forceinline__ void sgemm_body(char* sh,
                                           const float* __restrict__ W,
                                           const float* __restrict__ b1,
                                           float* __restrict__ out, int it,
                                           int bn, int bm) {
    constexpr int K  = (MODE == 3) ? 768 : 256;
    constexpr int NT = K / 32;
    typedef float (*tile_t)[32][33];
    tile_t Xs = (tile_t)sh;                     // [2][32][33]
    tile_t Ws = (tile_t)(sh + 2*32*33*4);       // [2][32][33]
    int tid = threadIdx.x;
    int r  = tid >> 3, c4 = (tid & 7) * 4;
    int tx = tid & 15, ty = tid >> 4;
    int m0 = bm*32 + r;
    int n0 = bn*32 + r;

    const float* wrow;
    if      (MODE == 0) wrow = W + (n0 < 256 ? (size_t)n0*512 : (size_t)(n0-256)*512 + 256);
    else if (MODE == 1) wrow = W + (size_t)n0*256;
    else if (MODE == 2) wrow = W + ((size_t)it*256 + (n0 & 255))*772 + (n0 >= 256 ? 256 : 0);
    else if (MODE == 3) wrow = W + (size_t)n0*768;
    else                wrow = W + (size_t)n0*256;

    const float* Xbase;
    if      (MODE == 0) Xbase = g_cf;
    else if (MODE == 1) Xbase = g_pg;
    else if (MODE == 2) Xbase = it ? g_x1 : g_cf;
    else if (MODE == 4) Xbase = g_ch;
    else                Xbase = g_cf;

    auto loadX = [&](int kb) -> float4 {
        if (MODE == 3) {
            int g = kb + c4;
            const float* src = (g < 256) ? g_cf : (g < 512 ? g_x1 : g_x2);
            return *(const float4*)(src + (size_t)m0*256 + (g & 255));
        }
        return *(const float4*)(Xbase + (size_t)m0*256 + kb + c4);
    };

    float4 xv = loadX(0);
    float4 wv = *(const float4*)(wrow + c4);
    float a00 = 0.f, a01 = 0.f, a10 = 0.f, a11 = 0.f;

    for (int t = 0; t < NT; t++) {
        int cur = t & 1;
        Xs[cur][c4+0][r] = xv.x; Xs[cur][c4+1][r] = xv.y;
        Xs[cur][c4+2][r] = xv.z; Xs[cur][c4+3][r] = xv.w;
        Ws[cur][c4+0][r] = wv.x; Ws[cur][c4+1][r] = wv.y;
        Ws[cur][c4+2][r] = wv.z; Ws[cur][c4+3][r] = wv.w;
        __syncthreads();
        if (t + 1 < NT) {
            xv = loadX((t+1)*32);
            wv = *(const float4*)(wrow + (t+1)*32 + c4);
        }
        #pragma unroll
        for (int k = 0; k < 32; k++) {
            float ax = Xs[cur][k][ty*2], ay = Xs[cur][k][ty*2+1];
            float bx = Ws[cur][k][tx*2], by = Ws[cur][k][tx*2+1];
            a00 += ax*bx; a01 += ax*by;
            a10 += ay*bx; a11 += ay*by;
        }
        if (t + 1 < NT) __syncthreads();
    }

    int m = bm*32 + ty*2, n = bn*32 + tx*2;
    float accs[2][2] = {{a00, a01}, {a10, a11}};
    #pragma unroll
    for (int mi = 0; mi < 2; mi++) {
        #pragma unroll
        for (int ni = 0; ni < 2; ni++) {
            int mm = m + mi, nn = n + ni;
            float v = accs[mi][ni];
            if      (MODE == 0) g_AB[mm*512 + nn] = (nn >= 256) ? v + b1[nn-256] : v;
            else if (MODE == 1) g_gy[mm*256 + nn] = v + b1[nn];
            else if (MODE == 2) g_UV[mm*512 + nn] = (nn < 256) ? v + b1[it*256 + nn] : v;
            else if (MODE == 3) g_ch[mm*256 + nn] = lrelu(v + b1[nn]);
            else                out [mm*256 + nn] = lrelu(v + b1[nn]);
        }
    }
}

// ---------------- heads body: one warp per (i, o) ---------------------------
__device__ __forceinline__ void heads_body(const float* __restrict__ We,  const float* __restrict__ be,
                                           const float* __restrict__ Ws,  const float* __restrict__ bs,
                                           const float* __restrict__ Wsi, const float* __restrict__ bsi,
                                           float* __restrict__ o_sem, float* __restrict__ o_semins,
                                           float* __restrict__ o_exists, int i, int oy) {
    int lane = threadIdx.x & 31, warp = threadIdx.x >> 5;
    int o = oy * 8 + warp;
    if (o > SN + PN) return;
    const float* w; float bias;
    if (o < SN)           { w = Ws  + o*HN;       bias = bs[o]; }
    else if (o < SN + PN) { w = Wsi + (o-SN)*HN;  bias = bsi[o-SN]; }
    else                  { w = We;               bias = be[0]; }
    float4 x0 = *(const float4*)&g_cf[i*HN + lane*4];
    float4 x1 = *(const float4*)&g_cf[i*HN + 128 + lane*4];
    float4 w0 = *(const float4*)&w[lane*4];
    float4 w1 = *(const float4*)&w[128 + lane*4];
    float s = w0.x*x0.x + w0.y*x0.y + w0.z*x0.z + w0.w*x0.w
            + w1.x*x1.x + w1.y*x1.y + w1.z*x1.z + w1.w*x1.w;
    #pragma unroll
    for (int q = 16; q; q >>= 1) s += __shfl_xor_sync(0xffffffffu, s, q);
    if (lane == 0) {
        s += bias;
        if (o < SN)           o_sem[i*SN + o] = s;
        else if (o < SN + PN) o_semins[i*PN + (o-SN)] = s;
        else { o_exists[i] = s; g_ok[i] = (s > 0.f) ? 1 : 0; }
    }
}

// ---------------- gemm body: E = el @ W3^T, BK=32, reg pipeline ------------
__device__ __forceinline__ void gemm_body(char* sh, const float* __restrict__ Wne,
                                          int bm, int bn) {
    if (g_ok[bm] == 0) return;
    typedef float (*buf_t)[BK*ST];
    buf_t As = (buf_t)sh;                       // [2][BK*ST]
    buf_t Bs = (buf_t)(sh + 2*BK*ST*4);
    int tid = threadIdx.x;
    int tx = tid & 15, ty = tid >> 4;

    float4 va[4], vb[4];
    int lm[4], lc[4];
    #pragma unroll
    for (int q = 0; q < 4; q++) { int l = tid + 256*q; lm[q] = l >> 3; lc[q] = (l & 7)*4; }

    auto ld = [&](int kb) {
        #pragma unroll
        for (int q = 0; q < 4; q++) {
            float4 a = *(const float4*)&g_AB[bm*512 + kb + lc[q]];
            float4 b = *(const float4*)&g_AB[lm[q]*512 + 256 + kb + lc[q]];
            va[q].x = lrelu(a.x + b.x);
            va[q].y = lrelu(a.y + b.y);
            va[q].z = lrelu(a.z + b.z);
            va[q].w = lrelu(a.w + b.w);
            int ng = bn*128 + lm[q];
            vb[q] = *(const float4*)&Wne[(size_t)ng*772 + 512 + kb + lc[q]];
        }
    };
    auto sts = [&](int s) {
        #pragma unroll
        for (int q = 0; q < 4; q++) {
            As[s][(lc[q]+0)*ST + lm[q]] = va[q].x;
            As[s][(lc[q]+1)*ST + lm[q]] = va[q].y;
            As[s][(lc[q]+2)*ST + lm[q]] = va[q].z;
            As[s][(lc[q]+3)*ST + lm[q]] = va[q].w;
            Bs[s][(lc[q]+0)*ST + lm[q]] = vb[q].x;
            Bs[s][(lc[q]+1)*ST + lm[q]] = vb[q].y;
            Bs[s][(lc[q]+2)*ST + lm[q]] = vb[q].z;
            Bs[s][(lc[q]+3)*ST + lm[q]] = vb[q].w;
        }
    };

    float2 c[8][4];
    #pragma unroll
    for (int a = 0; a < 8; a++)
        #pragma unroll
        for (int q = 0; q < 4; q++) c[a][q] = make_float2(0.f, 0.f);

    ld(0);
    sts(0);
    constexpr int NT = HN / BK;
    for (int t = 0; t < NT; t++) {
        int cur = t & 1;
        __syncthreads();
        if (t + 1 < NT) ld((t+1)*BK);

        float4 fa[2][2], fb[2][2];
        fa[0][0] = *(const float4*)&As[cur][ty*4];
        fa[0][1] = *(const float4*)&As[cur][ty*4 + 64];
        fb[0][0] = *(const float4*)&Bs[cur][tx*4];
        fb[0][1] = *(const float4*)&Bs[cur][tx*4 + 64];
        #pragma unroll
        for (int k = 0; k < BK; k++) {
            int pb = k & 1, nb2 = pb ^ 1;
            if (k + 1 < BK) {
                fa[nb2][0] = *(const float4*)&As[cur][(k+1)*ST + ty*4];
                fa[nb2][1] = *(const float4*)&As[cur][(k+1)*ST + ty*4 + 64];
                fb[nb2][0] = *(const float4*)&Bs[cur][(k+1)*ST + tx*4];
                fb[nb2][1] = *(const float4*)&Bs[cur][(k+1)*ST + tx*4 + 64];
            }
            float am[8] = {fa[pb][0].x, fa[pb][0].y, fa[pb][0].z, fa[pb][0].w,
                           fa[pb][1].x, fa[pb][1].y, fa[pb][1].z, fa[pb][1].w};
            float2 bl[4] = {make_float2(fb[pb][0].x, fb[pb][0].y),
                            make_float2(fb[pb][0].z, fb[pb][0].w),
                            make_float2(fb[pb][1].x, fb[pb][1].y),
                            make_float2(fb[pb][1].z, fb[pb][1].w)};
            #pragma unroll
            for (int mi = 0; mi < 8; mi++) {
                float2 a2 = make_float2(am[mi], am[mi]);
                #pragma unroll
                for (int qn = 0; qn < 4; qn++)
                    c[mi][qn] = fma2(a2, bl[qn], c[mi][qn]);
            }
        }
        if (t + 1 < NT) sts(cur ^ 1);
    }
    #pragma unroll
    for (int mi = 0; mi < 8; mi++) {
        int m = bm*128 + ty*4 + (mi>>2)*64 + (mi&3);
        float* Erow = g_E + (size_t)m*512 + bn*128;
        float4 v0, v1;
        v0.x = c[mi][0].x; v0.y = c[mi][0].y; v0.z = c[mi][1].x; v0.w = c[mi][1].y;
        v1.x = c[mi][2].x; v1.y = c[mi][2].y; v1.z = c[mi][3].x; v1.w = c[mi][3].y;
        *(float4*)&Erow[tx*4]      = v0;
        *(float4*)&Erow[tx*4 + 64] = v1;
    }
}

// ---------------- el body: edge logits ------------------------------------
__device__ __forceinline__ void el_body(char* sh, const float* __restrict__ Wee,
                                        const float* __restrict__ bee,
                                        float* __restrict__ o_logits, int i) {
    float* sA = (float*)sh;                     // 256
    float* sW = sA + 256;                       // 1024
    float* sB = sW + 1024;                      // 128*33
    float* sP = sB + 128*33;                    // 1024
    int t = threadIdx.x;
    int j = t & 127, half = t >> 7;
    sA[t] = g_AB[i*512 + t];
    #pragma unroll
    for (int l = t; l < 1024; l += 256) sW[l] = Wee[l];
    float acc0 = 0.f, acc1 = 0.f, acc2 = 0.f, acc3 = 0.f;
    for (int c0 = 0; c0 < 256; c0 += 32) {
        __syncthreads();
        #pragma unroll
        for (int idx = t; idx < 1024; idx += 256) {
            int jj = idx >> 3, f4 = (idx & 7) * 4;
            float4 v = *(const float4*)&g_AB[jj*512 + 256 + c0 + f4];
            sB[jj*33 + f4+0] = v.x; sB[jj*33 + f4+1] = v.y;
            sB[jj*33 + f4+2] = v.z; sB[jj*33 + f4+3] = v.w;
        }
        __syncthreads();
        int h0 = half*16;
        #pragma unroll
        for (int hh = 0; hh < 16; hh++) {
            int h = h0 + hh;
            float e = lrelu(sA[c0+h] + sB[j*33 + h]);
            acc0 += e * sW[        c0+h];
            acc1 += e * sW[256  + c0+h];
            acc2 += e * sW[512  + c0+h];
            acc3 += e * sW[768  + c0+h];
        }
    }
    sP[(j*2+half)*4 + 0] = acc0;
    sP[(j*2+half)*4 + 1] = acc1;
    sP[(j*2+half)*4 + 2] = acc2;
    sP[(j*2+half)*4 + 3] = acc3;
    __syncthreads();
    if (t < 128) {
        float4 o;
        o.x = sP[t*8+0] + sP[t*8+4] + bee[0];
        o.y = sP[t*8+1] + sP[t*8+5] + bee[1];
        o.z = sP[t*8+2] + sP[t*8+6] + bee[2];
        o.w = sP[t*8+3] + sP[t*8+7] + bee[3];
        *(float4*)&o_logits[(i*128 + t)*4] = o;
    }
}

// ---------------- gn body: groupnorm + lrelu -------------------------------
__device__ __forceinline__ void gn_body(char* sh, const float* __restrict__ gw,
                                        const float* __restrict__ gb,
                                        float* __restrict__ outg, int i) {
    float* sy = (float*)sh;       // 256
    float* sm = sy + 256;         // 32
    float* sv = sm + 32;          // 32
    int h = threadIdx.x;
    float s = g_gy[i*HN + h];
    sy[h] = s;
    __syncthreads();
    if (h < 32) {
        float m = 0.f, v = 0.f;
        #pragma unroll
        for (int q = 0; q < 8; q++) { float y = sy[h*8+q]; m += y; v += y*y; }
        m *= 0.125f; v = v*0.125f - m*m;
        sm[h] = m; sv[h] = rsqrtf(v + 1e-5f);
    }
    __syncthreads();
    float xn = (s - sm[h>>3]) * sv[h>>3] * gw[h] + gb[h];
    outg[i*HN + h] = lrelu(xn);
}

// ---------------- warm body: pull UV-it1 Wne region into L2 ----------------
__device__ __forceinline__ void warm_body(const float* __restrict__ Wne, int wb) {
    int t = threadIdx.x;
    int row = 256 + wb*4 + (t >> 6);
    int c0 = (t & 63) * 8;
    const float* src = Wne + (size_t)row*772 + c0;
    float4 a = *(const float4*)src;
    float4 b = *(const float4*)(src + 4);
    g_warm[wb*256 + t] = a.x + a.y + a.z + a.w + b.x + b.y + b.z + b.w;
}

// ---------------- L2: fused AB-sgemm + geo-sgemm + UV0 + heads -------------
__global__ void __launch_bounds__(256) k_stage2(
        const float* __restrict__ Wel, const float* __restrict__ bel,
        const float* __restrict__ Wgc, const float* __restrict__ bgc,
        const float* __restrict__ Wne, const float* __restrict__ bne,
        const float* __restrict__ We,  const float* __restrict__ be,
        const float* __restrict__ Ws,  const float* __restrict__ bs,
        const float* __restrict__ Wsi, const float* __restrict__ bsi,
        float* __restrict__ o_sem, float* __restrict__ o_semins,
        float* __restrict__ o_exists) {
    __shared__ __align__(16) char sh[2*2*32*33*4];
    int bid = blockIdx.x;
    if (bid < 64) {
        sgemm_body<0>(sh, Wel, bel, nullptr, 0, bid & 15, bid >> 4);
    } else if (bid < 128) {
        int b = bid - 64;
        sgemm_body<2>(sh, Wne, bne, nullptr, 0, b & 15, b >> 4);   // U|V it=0
    } else if (bid < 160) {
        int b = bid - 128;
        sgemm_body<1>(sh, Wgc, bgc, nullptr, 0, b & 7, b >> 3);
    } else {
        int hb = bid - 160;          // 0..1151
        heads_body(We, be, Ws, bs, Wsi, bsi, o_sem, o_semins, o_exists,
                   hb & 127, hb >> 7);
    }
}

// ---------------- L3: fused E-gemm + el + gn + L2-warm ---------------------
__global__ void __launch_bounds__(256, 2) k_stage3(
        const float* __restrict__ Wne,
        const float* __restrict__ Wee, const float* __restrict__ bee,
        float* __restrict__ o_logits,
        const float* __restrict__ gw, const float* __restrict__ gb,
        float* __restrict__ o_geo) {
    __shared__ __align__(16) char sh[2*2*BK*ST*4];
    int bid = blockIdx.x;
    if (bid < 512) {
        gemm_body(sh, Wne, bid >> 2, bid & 3);
    } else if (bid < 640) {
        el_body(sh, Wee, bee, o_logits, bid - 512);
    } else if (bid < 768) {
        gn_body(sh, gw, gb, o_geo, bid - 640);
    } else {
        warm_body(Wne, bid - 768);
    }
}

// ---------------- standalone sgemm kernel (UV1 / heads1 / heads2) ----------
template<int MODE>
__global__ void __launch_bounds__(256) k_sgemm(const float* __restrict__ W,
                                               const float* __restrict__ b1,
                                               float* __restrict__ out, int it) {
    __shared__ __align__(16) char sh[2*2*32*33*4];
    sgemm_body<MODE>(sh, W, b1, out, it, blockIdx.x, blockIdx.y);
}

// ---------------- masked max-reduction: 4-way j split + dual accumulator ---
__global__ void __launch_bounds__(1024) k_reduce(const float* __restrict__ o_logits,
                                                 const float* __restrict__ Wne, int it) {
    int i = blockIdx.x;
    int tid = threadIdx.x;
    int h = tid & 255, jh = tid >> 8;          // jh = 0..3
    float* xout = (it == 0) ? g_x1 : g_x2;
    __shared__ float slog[CN*TN];
    __shared__ float sP[4*HN];
    if (tid < CN*TN) {
        float v = o_logits[i*CN*TN + tid];
        slog[tid] = g_ok[tid >> 2] ? v : -1.f;
    }
    __syncthreads();
    if (!g_ok[i]) { if (jh == 0) xout[i*HN + h] = 0.f; return; }
    const float* wr = Wne + ((size_t)it*HN + h)*772 + 768;
    float w40 = wr[0], w41 = wr[1], w42 = wr[2], w43 = wr[3];
    float uh = g_UV[i*512 + h];
    const float* Ep = g_E + (size_t)i*CN*512 + it*HN + h;
    const float NEGINF = __int_as_float(0xff800000);
    float accA = NEGINF, accB = NEGINF;
    int j0 = jh * 32;
    #pragma unroll
    for (int jj = 0; jj < 16; jj++) {
        int ja = j0 + jj, jb = j0 + 16 + jj;
        float Ea = Ep[(size_t)ja*512];
        float Eb = Ep[(size_t)jb*512];
        float Va = g_UV[ja*512 + 256 + h];
        float Vb = g_UV[jb*512 + 256 + h];
        float a0 = slog[ja*4+0], a1 = slog[ja*4+1], a2 = slog[ja*4+2], a3 = slog[ja*4+3];
        float c0 = slog[jb*4+0], c1 = slog[jb*4+1], c2 = slog[jb*4+2], c3 = slog[jb*4+3];
        float ba0 = a0 > 0.f ? a0*w40 : NEGINF;
        float ba1 = a1 > 0.f ? a1*w41 : NEGINF;
        float ba2 = a2 > 0.f ? a2*w42 : NEGINF;
        float ba3 = a3 > 0.f ? a3*w43 : NEGINF;
        float bb0 = c0 > 0.f ? c0*w40 : NEGINF;
        float bb1 = c1 > 0.f ? c1*w41 : NEGINF;
        float bb2 = c2 > 0.f ? c2*w42 : NEGINF;
        float bb3 = c3 > 0.f ? c3*w43 : NEGINF;
        float bestA = fmaxf(fmaxf(ba0, ba1), fmaxf(ba2, ba3));
        float bestB = fmaxf(fmaxf(bb0, bb1), fmaxf(bb2, bb3));
        accA = fmaxf(accA, bestA + (Ea + Va));
        accB = fmaxf(accB, bestB + (Eb + Vb));
    }
    sP[jh*HN + h] = fmaxf(accA, accB) + uh;
    __syncthreads();
    if (jh == 0) {
        float m = fmaxf(fmaxf(sP[h], sP[HN + h]), fmaxf(sP[2*HN + h], sP[3*HN + h]));
        xout[i*HN + h] = fmaxf(m, 0.f);
    }
}

// ---------------- launch ---------------------------------------------------
extern "C" void kernel_launch(void* const* d_in, const int* in_sizes, int n_in,
                              void* d_out, int out_size) {
    const float* psf = (const float*)d_in[0];
    const float* pgf = (const float*)d_in[1];
    const float* Wp  = (const float*)d_in[2];
    const float* bp  = (const float*)d_in[3];
    const float* We  = (const float*)d_in[4];
    const float* be  = (const float*)d_in[5];
    const float* Ws  = (const float*)d_in[6];
    const float* bs  = (const float*)d_in[7];
    const float* Wsi = (const float*)d_in[8];
    const float* bsi = (const float*)d_in[9];
    const float* Wel = (const float*)d_in[10];
    const float* bel = (const float*)d_in[11];
    const float* Wee = (const float*)d_in[12];
    const float* bee = (const float*)d_in[13];
    const float* Wne = (const float*)d_in[14];
    const float* bne = (const float*)d_in[15];
    const float* Wc  = (const float*)d_in[16];
    const float* bc  = (const float*)d_in[17];
    const float* Wc2 = (const float*)d_in[18];
    const float* bc2 = (const float*)d_in[19];
    const float* Wgc = (const float*)d_in[20];
    const float* bgc = (const float*)d_in[21];
    const float* Wgp = (const float*)d_in[22];
    const float* bgp = (const float*)d_in[23];
    const float* gw  = (const float*)d_in[24];
    const float* gb  = (const float*)d_in[25];

    float* out       = (float*)d_out;
    float* o_child   = out;                    // 32768
    float* o_geo     = out + 32768;            // 32768
    float* o_sem     = out + 65536;            // 7296
    float* o_semins  = out + 72832;            // 1280
    float* o_exists  = out + 74112;            // 128
    float* o_logits  = out + 74240;            // 65536

    k_gemv_big<<<1024, 256>>>(psf, Wp, bp, pgf, Wgp, bgp);              // 1
    k_stage2<<<1312, 256>>>(Wel, bel, Wgc, bgc, Wne, bne, We, be,
                            Ws, bs, Wsi, bsi, o_sem, o_semins, o_exists); // 2 (+UV0)
    k_stage3<<<832, 256>>>(Wne, Wee, bee, o_logits, gw, gb, o_geo);     // 3 (+warm)
    k_reduce<<<CN, 1024>>>(o_logits, Wne, 0);                           // 4
    k_sgemm<2><<<dim3(16, 4), 256>>>(Wne, bne, nullptr, 1);             // 5  U|V it=1
    k_reduce<<<CN, 1024>>>(o_logits, Wne, 1);                           // 6
    k_sgemm<3><<<dim3(8, 4), 256>>>(Wc, bc, nullptr, 0);                // 7  head1
    k_sgemm<4><<<dim3(8, 4), 256>>>(Wc2, bc2, o_child, 0);              // 8  head2
}